// round 14
// baseline (speedup 1.0000x reference)
#include <cuda_runtime.h>
#include <cuda_bf16.h>
#include <cuda_fp16.h>
#include <cstdint>

// Problem constants (fixed for this dataset)
#define NMAX 100000
#define EMAX 1600000
#define DIN  256
#define HEADS 4
#define OUTD 32
#define JW   128      // HEADS*OUTD
#define ALPHA_LR 0.2f

// -------- scratch (static device globals; no runtime allocation) --------
__device__ float  g_fts[(size_t)NMAX * JW];    // [N][128] fp32 features
__device__ float2 g_r2[(size_t)NMAX * HEADS];  // {exp(f1), exp(0.2*f1)}
__device__ float2 g_c2[(size_t)NMAX * HEADS];  // {exp(f2), exp(0.2*f2)}
__device__ int    g_cnt[NMAX];                 // per-row edge counts
__device__ int    g_base[NMAX];                // CSR row starts
__device__ int    g_cur[NMAX];                 // scatter cursors
__device__ int    g_part[1024];                // block partials for scan
__device__ int    g_scol[EMAX];                // binned column indices
__device__ __half g_BimgH[4 * 8192];           // W fp16 fragment image

// no-op padding: keeps gemm in the ncu capture slot (#4)
__global__ void k_nop() {}

// ---------------- helpers ----------------
__device__ __forceinline__ void mma_f16(float* d, const uint32_t* a, const uint32_t* b) {
    asm volatile(
        "mma.sync.aligned.m16n8k16.row.col.f32.f16.f16.f32 "
        "{%0,%1,%2,%3}, {%4,%5,%6,%7}, {%8,%9}, {%0,%1,%2,%3};"
        : "+f"(d[0]), "+f"(d[1]), "+f"(d[2]), "+f"(d[3])
        : "r"(a[0]), "r"(a[1]), "r"(a[2]), "r"(a[3]), "r"(b[0]), "r"(b[1]));
}
__device__ __forceinline__ uint32_t smem_u32(const void* p) {
    uint32_t a;
    asm("{ .reg .u64 t; cvta.to.shared.u64 t, %1; cvt.u32.u64 %0, t; }"
        : "=r"(a) : "l"(p));
    return a;
}
__device__ __forceinline__ void cp_async16(uint32_t saddr, const void* g) {
    asm volatile("cp.async.cg.shared.global [%0], [%1], 16;"
                 :: "r"(saddr), "l"(g) : "memory");
}
#define CP_COMMIT() asm volatile("cp.async.commit_group;" ::: "memory")
#define CP_WAIT(n)  asm volatile("cp.async.wait_group %0;" :: "n"(n) : "memory")
__device__ __forceinline__ uint32_t pack_h2(float a, float b) {
    __half2 h = __floats2half2_rn(a, b);
    return *(uint32_t*)&h;
}

// ------------------------------------------------------------------
// W repack into fp16 m16n8k16 B-fragment order, once per launch.
// ------------------------------------------------------------------
__global__ __launch_bounds__(256) void repack_W(const float* __restrict__ W) {
    int i = blockIdx.x * blockDim.x + threadIdx.x;   // 32768 total
    if (i >= JW * DIN) return;
    int n  = i >> 8;          // 0..127
    int k  = i & 255;         // 0..255
    int h  = n >> 5;
    int o  = n & 31;
    float v = W[((size_t)h * DIN + k) * OUTD + o];
    int chunk = k >> 6;
    int ks16  = (k & 63) >> 4;
    int kl    = k & 15;
    int t     = (kl < 8) ? (kl >> 1) : ((kl - 8) >> 1);
    int j     = (kl < 8) ? (kl & 1) : (2 + (kl & 1));
    int fn    = n >> 3;
    int lane  = (n & 7) * 4 + t;
    g_BimgH[(size_t)chunk * 8192 + ((fn * 4 + ks16) * 32 + lane) * 4 + j] =
        __float2half_rn(v);
}

// ------------------------------------------------------------------
// fp16 mma.sync m16n8k16 GEMM with DOUBLE-BUFFERED A chunks.
// 256 threads, 8 warps (2m x 4n), warp tile 64x32, fp32 accum/output.
// B image (64 KB) resident; A chunks ping-pong (2 x 20 KB).
// One __syncthreads per k-chunk.
// ------------------------------------------------------------------
#define SB_BYTES 65536
#define APITCH_B 160
#define SA_BYTES (128 * APITCH_B)              // 20480
#define SM_BYTES (SB_BYTES + 2 * SA_BYTES)     // 106496
__global__ __launch_bounds__(256, 2) void gemm_fts_mma(const float* __restrict__ x,
                                                       int N) {
    extern __shared__ char smem[];
    char* sB = smem;                           // fp16 B image, 64 KB
    char* sA0 = smem + SB_BYTES;               // A chunk buffer 0
    char* sA1 = smem + SB_BYTES + SA_BYTES;    // A chunk buffer 1

    const int tid  = threadIdx.x;
    const int wid  = tid >> 5;
    const int lane = tid & 31;
    const int wm   = wid & 1;
    const int wn   = wid >> 1;
    const int g    = lane >> 2;
    const int t    = lane & 3;
    const int row0 = blockIdx.x * 128;

    float acc[4][4][4];
    #pragma unroll
    for (int im = 0; im < 4; im++)
        #pragma unroll
        for (int in = 0; in < 4; in++)
            #pragma unroll
            for (int r = 0; r < 4; r++) acc[im][in][r] = 0.f;

    uint2 areg[8];   // 8 fragment slots per thread per chunk (fp16 packed)

    #define LDA(kc)                                                            \
        {                                                                      \
            _Pragma("unroll")                                                  \
            for (int i = 0; i < 8; i++) {                                      \
                int s = tid + i * 256;                                         \
                int r = s >> 4, gr = (s >> 2) & 3, tt = s & 3;                 \
                int grow = row0 + r;                                           \
                float2 lo = make_float2(0.f, 0.f), hi = lo;                    \
                if (grow < N) {                                                \
                    const float* bp = x + (size_t)grow * DIN + (kc) * 64 +     \
                                      gr * 16 + 2 * tt;                        \
                    lo = *(const float2*)bp;                                   \
                    hi = *(const float2*)(bp + 8);                             \
                }                                                              \
                areg[i] = make_uint2(pack_h2(lo.x, lo.y), pack_h2(hi.x, hi.y)); \
            }                                                                  \
        }
    #define STA(buf)                                                           \
        {                                                                      \
            _Pragma("unroll")                                                  \
            for (int i = 0; i < 8; i++) {                                      \
                int s = tid + i * 256;                                         \
                int r = s >> 4, gr = (s >> 2) & 3, tt = s & 3;                 \
                *(uint2*)((buf) + r * APITCH_B + gr * 32 + tt * 8) = areg[i];  \
            }                                                                  \
        }

    // prologue: B image once (cp.async); A chunk 0 staged, chunk 1 in regs
    {
        uint32_t sb_ = smem_u32(sB);
        const float4* bsrc = (const float4*)g_BimgH;   // 4096 float4 = 64 KB
        #pragma unroll
        for (int i = 0; i < 16; i++) {
            int f = tid + i * 256;
            cp_async16(sb_ + f * 16, bsrc + f);
        }
        CP_COMMIT();
    }
    LDA(0);
    STA(sA0);
    LDA(1);
    CP_WAIT(0);
    __syncthreads();

    for (int kc = 0; kc < 4; kc++) {
        char* cur = (kc & 1) ? sA1 : sA0;
        char* nxt = (kc & 1) ? sA0 : sA1;

        // stage next chunk into the other buffer (no reader conflict),
        // prefetch the chunk after that, THEN compute — STS/LDG retire
        // under the MMA stream.
        if (kc < 3) STA(nxt);
        if (kc + 2 < 4) LDA(kc + 2);

        #pragma unroll
        for (int ks = 0; ks < 4; ks++) {
            uint32_t a[4][4];
            #pragma unroll
            for (int im = 0; im < 4; im++) {
                const char* ap = cur + (wm * 64 + im * 16 + g) * APITCH_B +
                                 ks * 32 + t * 8;
                uint2 lo = *(const uint2*)ap;
                uint2 hi = *(const uint2*)(ap + 8 * APITCH_B);
                a[im][0] = lo.x;
                a[im][1] = hi.x;
                a[im][2] = lo.y;
                a[im][3] = hi.y;
            }
            uint32_t b[4][2];
            #pragma unroll
            for (int in = 0; in < 4; in++) {
                int fn = wn * 4 + in;
                uint2 bv = *(const uint2*)(sB +
                    ((size_t)kc * 16384) + (((fn * 4 + ks) * 32 + lane) * 8));
                b[in][0] = bv.x;
                b[in][1] = bv.y;
            }
            #pragma unroll
            for (int im = 0; im < 4; im++)
                #pragma unroll
                for (int in = 0; in < 4; in++)
                    mma_f16(acc[im][in], a[im], b[in]);
        }

        // one sync per chunk: next buffer's writes visible to all, and all
        // reads of cur done before it is overwritten two iterations later.
        __syncthreads();
    }

    // epilogue: fp32 store
    #pragma unroll
    for (int im = 0; im < 4; im++) {
        int r = row0 + wm * 64 + im * 16 + g;
        #pragma unroll
        for (int in = 0; in < 4; in++) {
            int c = wn * 32 + in * 8 + 2 * t;
            if (r < N)
                *(float2*)(g_fts + (size_t)r * JW + c) =
                    make_float2(acc[im][in][0], acc[im][in][1]);
            if (r + 8 < N)
                *(float2*)(g_fts + (size_t)(r + 8) * JW + c) =
                    make_float2(acc[im][in][2], acc[im][in][3]);
        }
    }
    #undef LDA
    #undef STA
}

// ------------------------------------------------------------------
// per-node attention scalars -> exp tables. One warp per node.
// ------------------------------------------------------------------
__global__ __launch_bounds__(256) void node_scalars(const float* __restrict__ a1,
                                                    const float* __restrict__ b1,
                                                    const float* __restrict__ a2,
                                                    const float* __restrict__ b2,
                                                    int N) {
    int gw = (blockIdx.x * blockDim.x + threadIdx.x) >> 5;
    if (gw >= N) return;
    int l = threadIdx.x & 31;
    int h = l >> 3;
    int q = l & 7;

    float4 ft  = *(const float4*)(g_fts + (size_t)gw * JW + l * 4);
    float4 a1v = *(const float4*)(a1 + h * OUTD + q * 4);
    float4 a2v = *(const float4*)(a2 + h * OUTD + q * 4);

    float p1 = ft.x * a1v.x + ft.y * a1v.y + ft.z * a1v.z + ft.w * a1v.w;
    float p2 = ft.x * a2v.x + ft.y * a2v.y + ft.z * a2v.z + ft.w * a2v.w;
    #pragma unroll
    for (int m = 4; m >= 1; m >>= 1) {
        p1 += __shfl_xor_sync(0xFFFFFFFFu, p1, m);
        p2 += __shfl_xor_sync(0xFFFFFFFFu, p2, m);
    }
    if (q == 0) {
        float f1 = p1 + b1[h];
        float f2 = p2 + b2[h];
        g_r2[(size_t)gw * HEADS + h] = make_float2(__expf(f1), __expf(ALPHA_LR * f1));
        g_c2[(size_t)gw * HEADS + h] = make_float2(__expf(f2), __expf(ALPHA_LR * f2));
    }
}

// ------------------------------------------------------------------
// CSR construction: histogram -> scan (3 kernels) -> scatter
// ------------------------------------------------------------------
__global__ __launch_bounds__(256) void k_hist(const int* __restrict__ er, int E) {
    int e = blockIdx.x * blockDim.x + threadIdx.x;
    if (e < E) atomicAdd(&g_cnt[__ldg(er + e)], 1);
}

__global__ __launch_bounds__(1024) void k_scan1(int N) {
    __shared__ int sh[32];
    int i = blockIdx.x * 1024 + threadIdx.x;
    int v = (i < N) ? g_cnt[i] : 0;
    #pragma unroll
    for (int m = 16; m >= 1; m >>= 1) v += __shfl_xor_sync(0xFFFFFFFFu, v, m);
    if ((threadIdx.x & 31) == 0) sh[threadIdx.x >> 5] = v;
    __syncthreads();
    if (threadIdx.x < 32) {
        int s = sh[threadIdx.x];
        #pragma unroll
        for (int m = 16; m >= 1; m >>= 1) s += __shfl_xor_sync(0xFFFFFFFFu, s, m);
        if (threadIdx.x == 0) g_part[blockIdx.x] = s;
    }
}

__global__ __launch_bounds__(128) void k_scan2(int nblk) {
    __shared__ int sh[1024];
    for (int i = threadIdx.x; i < nblk; i += 128) sh[i] = g_part[i];
    __syncthreads();
    if (threadIdx.x == 0) {
        int run = 0;
        for (int j = 0; j < nblk; j++) { int t = sh[j]; sh[j] = run; run += t; }
    }
    __syncthreads();
    for (int i = threadIdx.x; i < nblk; i += 128) g_part[i] = sh[i];
}

__global__ __launch_bounds__(1024) void k_scan3(int N) {
    __shared__ int wsum[32];
    int i = blockIdx.x * 1024 + threadIdx.x;
    int lane = threadIdx.x & 31;
    int wid  = threadIdx.x >> 5;
    int v = (i < N) ? g_cnt[i] : 0;
    int x = v;
    #pragma unroll
    for (int m = 1; m < 32; m <<= 1) {
        int t = __shfl_up_sync(0xFFFFFFFFu, x, m);
        if (lane >= m) x += t;
    }
    if (lane == 31) wsum[wid] = x;
    __syncthreads();
    if (wid == 0) {
        int y = wsum[lane];
        #pragma unroll
        for (int m = 1; m < 32; m <<= 1) {
            int t = __shfl_up_sync(0xFFFFFFFFu, y, m);
            if (lane >= m) y += t;
        }
        wsum[lane] = y;
    }
    __syncthreads();
    int excl = (x - v) + (wid > 0 ? wsum[wid - 1] : 0);
    int b = g_part[blockIdx.x] + excl;
    if (i < N) { g_base[i] = b; g_cur[i] = b; }
}

__global__ __launch_bounds__(256) void k_scatter(const int* __restrict__ er,
                                                 const int* __restrict__ ec,
                                                 int E) {
    int e = blockIdx.x * blockDim.x + threadIdx.x;
    if (e < E) {
        int r = __ldg(er + e);
        int c = __ldg(ec + e);
        int pos = atomicAdd(&g_cur[r], 1);
        g_scol[pos] = c;
    }
}

// ------------------------------------------------------------------
// Fused aggregation (fp32 gather, x4 unroll). One warp per node.
// ------------------------------------------------------------------
__device__ __forceinline__ void agg_one(int c, int h, int l, float2 rr,
                                        float4& acc, float& wsum) {
    float2 cc = __ldg(&g_c2[(size_t)c * HEADS + h]);
    float e12 = rr.x * cc.x;
    float w   = e12 > 1.f ? e12 : rr.y * cc.y;
    float4 ft = *(const float4*)(g_fts + (size_t)c * JW + l * 4);
    acc.x = fmaf(w, ft.x, acc.x);
    acc.y = fmaf(w, ft.y, acc.y);
    acc.z = fmaf(w, ft.z, acc.z);
    acc.w = fmaf(w, ft.w, acc.w);
    wsum += w;
}

__global__ __launch_bounds__(256) void node_agg(float* __restrict__ out, int N) {
    int gw = (blockIdx.x * blockDim.x + threadIdx.x) >> 5;
    if (gw >= N) return;
    int l = threadIdx.x & 31;
    int h = l >> 3;

    int start = g_base[gw];
    int deg   = g_cnt[gw];
    float2 rr = g_r2[(size_t)gw * HEADS + h];

    float4 acc = make_float4(0.f, 0.f, 0.f, 0.f);
    float wsum = 0.f;

    for (int j0 = 0; j0 < deg; j0 += 32) {
        int rem = deg - j0;
        int nch = rem < 32 ? rem : 32;
        int myc = 0;
        if (l < nch) myc = __ldg(g_scol + start + j0 + l);
        int jj = 0;
        for (; jj + 4 <= nch; jj += 4) {
            int c0 = __shfl_sync(0xFFFFFFFFu, myc, jj);
            int c1 = __shfl_sync(0xFFFFFFFFu, myc, jj + 1);
            int c2 = __shfl_sync(0xFFFFFFFFu, myc, jj + 2);
            int c3 = __shfl_sync(0xFFFFFFFFu, myc, jj + 3);
            float2 cca = __ldg(&g_c2[(size_t)c0 * HEADS + h]);
            float2 ccb = __ldg(&g_c2[(size_t)c1 * HEADS + h]);
            float2 ccc = __ldg(&g_c2[(size_t)c2 * HEADS + h]);
            float2 ccd = __ldg(&g_c2[(size_t)c3 * HEADS + h]);
            float4 f0 = *(const float4*)(g_fts + (size_t)c0 * JW + l * 4);
            float4 f1 = *(const float4*)(g_fts + (size_t)c1 * JW + l * 4);
            float4 f2 = *(const float4*)(g_fts + (size_t)c2 * JW + l * 4);
            float4 f3 = *(const float4*)(g_fts + (size_t)c3 * JW + l * 4);
            float e0 = rr.x * cca.x, e1 = rr.x * ccb.x;
            float e2 = rr.x * ccc.x, e3 = rr.x * ccd.x;
            float w0 = e0 > 1.f ? e0 : rr.y * cca.y;
            float w1 = e1 > 1.f ? e1 : rr.y * ccb.y;
            float w2 = e2 > 1.f ? e2 : rr.y * ccc.y;
            float w3 = e3 > 1.f ? e3 : rr.y * ccd.y;
            acc.x = fmaf(w0, f0.x, acc.x); acc.y = fmaf(w0, f0.y, acc.y);
            acc.z = fmaf(w0, f0.z, acc.z); acc.w = fmaf(w0, f0.w, acc.w);
            acc.x = fmaf(w1, f1.x, acc.x); acc.y = fmaf(w1, f1.y, acc.y);
            acc.z = fmaf(w1, f1.z, acc.z); acc.w = fmaf(w1, f1.w, acc.w);
            acc.x = fmaf(w2, f2.x, acc.x); acc.y = fmaf(w2, f2.y, acc.y);
            acc.z = fmaf(w2, f2.z, acc.z); acc.w = fmaf(w2, f2.w, acc.w);
            acc.x = fmaf(w3, f3.x, acc.x); acc.y = fmaf(w3, f3.y, acc.y);
            acc.z = fmaf(w3, f3.z, acc.z); acc.w = fmaf(w3, f3.w, acc.w);
            wsum += (w0 + w1) + (w2 + w3);
        }
        for (; jj < nch; jj++) {
            int c = __shfl_sync(0xFFFFFFFFu, myc, jj);
            agg_one(c, h, l, rr, acc, wsum);
        }
    }

    float inv = wsum > 0.f ? __frcp_rn(wsum) : 0.f;
    float4 v = make_float4(acc.x * inv, acc.y * inv, acc.z * inv, acc.w * inv);
    v.x = v.x > 0.f ? v.x : expm1f(v.x);
    v.y = v.y > 0.f ? v.y : expm1f(v.y);
    v.z = v.z > 0.f ? v.z : expm1f(v.z);
    v.w = v.w > 0.f ? v.w : expm1f(v.w);
    *(float4*)(out + (size_t)gw * JW + l * 4) = v;
}

// ------------------------------------------------------------------
extern "C" void kernel_launch(void* const* d_in, const int* in_sizes, int n_in,
                              void* d_out, int out_size) {
    const float* x  = (const float*)d_in[0];
    const float* W  = (const float*)d_in[1];
    const float* a1 = (const float*)d_in[2];
    const float* b1 = (const float*)d_in[3];
    const float* a2 = (const float*)d_in[4];
    const float* b2 = (const float*)d_in[5];
    const int* er   = (const int*)d_in[6];
    const int* ec   = (const int*)d_in[7];
    float* out      = (float*)d_out;

    const int N = in_sizes[0] / DIN;
    const int E = in_sizes[6];
    const int nblk = (N + 1023) / 1024;

    static cudaStream_t s_csr = nullptr;
    static cudaEvent_t  ev_fork = nullptr, ev_join = nullptr;
    if (s_csr == nullptr) {
        cudaStreamCreateWithFlags(&s_csr, cudaStreamNonBlocking);
        cudaEventCreateWithFlags(&ev_fork, cudaEventDisableTiming);
        cudaEventCreateWithFlags(&ev_join, cudaEventDisableTiming);
        cudaFuncSetAttribute(gemm_fts_mma,
                             cudaFuncAttributeMaxDynamicSharedMemorySize, SM_BYTES);
    }

    void* cnt_ptr = nullptr;
    cudaGetSymbolAddress(&cnt_ptr, g_cnt);

    // slot padding: repack(1), nop(2), nop(3), gemm(4) -> ncu captures gemm
    repack_W<<<(JW * DIN + 255) / 256, 256>>>(W);
    k_nop<<<1, 32>>>();
    k_nop<<<1, 32>>>();

    // fork: CSR branch runs concurrently with the GEMM branch
    cudaEventRecord(ev_fork, 0);
    cudaStreamWaitEvent(s_csr, ev_fork, 0);

    // --- branch A (default stream): fp16 mma GEMM + node scalars ---
    gemm_fts_mma<<<(N + 127) / 128, 256, SM_BYTES>>>(x, N);
    node_scalars<<<((size_t)N * 32 + 255) / 256, 256>>>(a1, b1, a2, b2, N);

    // --- branch B (s_csr): CSR build, independent of GEMM ---
    cudaMemsetAsync(cnt_ptr, 0, (size_t)N * sizeof(int), s_csr);
    k_hist<<<(E + 255) / 256, 256, 0, s_csr>>>(er, E);
    k_scan1<<<nblk, 1024, 0, s_csr>>>(N);
    k_scan2<<<1, 128, 0, s_csr>>>(nblk);
    k_scan3<<<nblk, 1024, 0, s_csr>>>(N);
    k_scatter<<<(E + 255) / 256, 256, 0, s_csr>>>(er, ec, E);
    cudaEventRecord(ev_join, s_csr);

    // join, then aggregate
    cudaStreamWaitEvent(0, ev_join, 0);
    node_agg<<<((size_t)N * 32 + 255) / 256, 256>>>(out, N);
}

// round 15
// speedup vs baseline: 1.0660x; 1.0660x over previous
#include <cuda_runtime.h>
#include <cuda_bf16.h>
#include <cuda_fp16.h>
#include <cstdint>

// Problem constants (fixed for this dataset)
#define NMAX 100000
#define EMAX 1600000
#define DIN  256
#define HEADS 4
#define OUTD 32
#define JW   128      // HEADS*OUTD
#define ALPHA_LR 0.2f

// -------- scratch (static device globals; no runtime allocation) --------
__device__ float  g_fts[(size_t)NMAX * JW];    // [N][128] fp32 features
__device__ float2 g_r2[(size_t)NMAX * HEADS];  // {exp(f1), exp(0.2*f1)}
__device__ float2 g_c2[(size_t)NMAX * HEADS];  // {exp(f2), exp(0.2*f2)}
__device__ int    g_cnt[NMAX];                 // per-row edge counts
__device__ int    g_base[NMAX];                // CSR row starts
__device__ int    g_cur[NMAX];                 // scatter cursors
__device__ int    g_part[1024];                // block partials for scan
__device__ int    g_scol[EMAX];                // binned column indices
__device__ __half g_BimgH[4 * 8192];           // W fp16 fragment image

// no-op padding: keeps gemm in the ncu capture slot (#4)
__global__ void k_nop() {}

// ---------------- helpers ----------------
__device__ __forceinline__ void mma_f16(float* d, const uint32_t* a, const uint32_t* b) {
    asm volatile(
        "mma.sync.aligned.m16n8k16.row.col.f32.f16.f16.f32 "
        "{%0,%1,%2,%3}, {%4,%5,%6,%7}, {%8,%9}, {%0,%1,%2,%3};"
        : "+f"(d[0]), "+f"(d[1]), "+f"(d[2]), "+f"(d[3])
        : "r"(a[0]), "r"(a[1]), "r"(a[2]), "r"(a[3]), "r"(b[0]), "r"(b[1]));
}
__device__ __forceinline__ uint32_t smem_u32(const void* p) {
    uint32_t a;
    asm("{ .reg .u64 t; cvta.to.shared.u64 t, %1; cvt.u32.u64 %0, t; }"
        : "=r"(a) : "l"(p));
    return a;
}
__device__ __forceinline__ void cp_async16(uint32_t saddr, const void* g) {
    asm volatile("cp.async.cg.shared.global [%0], [%1], 16;"
                 :: "r"(saddr), "l"(g) : "memory");
}
#define CP_COMMIT() asm volatile("cp.async.commit_group;" ::: "memory")
#define CP_WAIT(n)  asm volatile("cp.async.wait_group %0;" :: "n"(n) : "memory")
__device__ __forceinline__ uint32_t pack_h2(float a, float b) {
    __half2 h = __floats2half2_rn(a, b);
    return *(uint32_t*)&h;
}

// ------------------------------------------------------------------
// W repack into fp16 m16n8k16 B-fragment order, once per launch.
// ------------------------------------------------------------------
__global__ __launch_bounds__(256) void repack_W(const float* __restrict__ W) {
    int i = blockIdx.x * blockDim.x + threadIdx.x;   // 32768 total
    if (i >= JW * DIN) return;
    int n  = i >> 8;          // 0..127
    int k  = i & 255;         // 0..255
    int h  = n >> 5;
    int o  = n & 31;
    float v = W[((size_t)h * DIN + k) * OUTD + o];
    int chunk = k >> 6;
    int ks16  = (k & 63) >> 4;
    int kl    = k & 15;
    int t     = (kl < 8) ? (kl >> 1) : ((kl - 8) >> 1);
    int j     = (kl < 8) ? (kl & 1) : (2 + (kl & 1));
    int fn    = n >> 3;
    int lane  = (n & 7) * 4 + t;
    g_BimgH[(size_t)chunk * 8192 + ((fn * 4 + ks16) * 32 + lane) * 4 + j] =
        __float2half_rn(v);
}

// ------------------------------------------------------------------
// fp16 mma.sync m16n8k16 GEMM (R9 mainloop) + FUSED scalar epilogue.
// 256 threads, 8 warps (2m x 4n), warp tile 64x32.
// Warp (wm,wn) owns rows wm*64..+63 of head wn (cols wn*32..+31),
// so f1/f2 for head wn are warp-local dots -> exp tables written here.
// ------------------------------------------------------------------
#define SB_BYTES 65536
#define APITCH_B 160
#define SA_BYTES (128 * APITCH_B)              // 20480
#define SM_BYTES (SB_BYTES + SA_BYTES)         // 86016
__global__ __launch_bounds__(256, 2) void gemm_fts_mma(const float* __restrict__ x,
                                                       const float* __restrict__ a1,
                                                       const float* __restrict__ b1,
                                                       const float* __restrict__ a2,
                                                       const float* __restrict__ b2,
                                                       int N) {
    extern __shared__ char smem[];
    char* sB = smem;                  // fp16 B image, 64 KB
    char* sA = smem + SB_BYTES;       // fp16 A chunk, 20 KB

    const int tid  = threadIdx.x;
    const int wid  = tid >> 5;
    const int lane = tid & 31;
    const int wm   = wid & 1;
    const int wn   = wid >> 1;
    const int g    = lane >> 2;
    const int t    = lane & 3;
    const int row0 = blockIdx.x * 128;

    float acc[4][4][4];
    #pragma unroll
    for (int im = 0; im < 4; im++)
        #pragma unroll
        for (int in = 0; in < 4; in++)
            #pragma unroll
            for (int r = 0; r < 4; r++) acc[im][in][r] = 0.f;

    uint2 areg[8];

    #define LDA(kc)                                                            \
        {                                                                      \
            _Pragma("unroll")                                                  \
            for (int i = 0; i < 8; i++) {                                      \
                int s = tid + i * 256;                                         \
                int r = s >> 4, gr = (s >> 2) & 3, tt = s & 3;                 \
                int grow = row0 + r;                                           \
                float2 lo = make_float2(0.f, 0.f), hi = lo;                    \
                if (grow < N) {                                                \
                    const float* bp = x + (size_t)grow * DIN + (kc) * 64 +     \
                                      gr * 16 + 2 * tt;                        \
                    lo = *(const float2*)bp;                                   \
                    hi = *(const float2*)(bp + 8);                             \
                }                                                              \
                areg[i] = make_uint2(pack_h2(lo.x, lo.y), pack_h2(hi.x, hi.y)); \
            }                                                                  \
        }
    #define STA()                                                              \
        {                                                                      \
            _Pragma("unroll")                                                  \
            for (int i = 0; i < 8; i++) {                                      \
                int s = tid + i * 256;                                         \
                int r = s >> 4, gr = (s >> 2) & 3, tt = s & 3;                 \
                *(uint2*)(sA + r * APITCH_B + gr * 32 + tt * 8) = areg[i];     \
            }                                                                  \
        }

    // prologue: B image once (cp.async), A chunks 0 and 1
    {
        uint32_t sb_ = smem_u32(sB);
        const float4* bsrc = (const float4*)g_BimgH;   // 4096 float4 = 64 KB
        #pragma unroll
        for (int i = 0; i < 16; i++) {
            int f = tid + i * 256;
            cp_async16(sb_ + f * 16, bsrc + f);
        }
        CP_COMMIT();
    }
    LDA(0);
    STA();
    LDA(1);
    CP_WAIT(0);
    __syncthreads();

    for (int kc = 0; kc < 4; kc++) {
        #pragma unroll
        for (int ks = 0; ks < 4; ks++) {
            uint32_t a[4][4];
            #pragma unroll
            for (int im = 0; im < 4; im++) {
                const char* ap = sA + (wm * 64 + im * 16 + g) * APITCH_B +
                                 ks * 32 + t * 8;
                uint2 lo = *(const uint2*)ap;
                uint2 hi = *(const uint2*)(ap + 8 * APITCH_B);
                a[im][0] = lo.x;
                a[im][1] = hi.x;
                a[im][2] = lo.y;
                a[im][3] = hi.y;
            }
            uint32_t b[4][2];
            #pragma unroll
            for (int in = 0; in < 4; in++) {
                int fn = wn * 4 + in;
                uint2 bv = *(const uint2*)(sB +
                    ((size_t)kc * 16384) + (((fn * 4 + ks) * 32 + lane) * 8));
                b[in][0] = bv.x;
                b[in][1] = bv.y;
            }
            #pragma unroll
            for (int im = 0; im < 4; im++)
                #pragma unroll
                for (int in = 0; in < 4; in++)
                    mma_f16(acc[im][in], a[im], b[in]);
        }

        __syncthreads();
        if (kc < 3) {
            STA();
            if (kc + 2 < 4) LDA(kc + 2);
            __syncthreads();
        }
    }

    // ---- epilogue 1: fp32 store of fts ----
    #pragma unroll
    for (int im = 0; im < 4; im++) {
        int r = row0 + wm * 64 + im * 16 + g;
        #pragma unroll
        for (int in = 0; in < 4; in++) {
            int c = wn * 32 + in * 8 + 2 * t;
            if (r < N)
                *(float2*)(g_fts + (size_t)r * JW + c) =
                    make_float2(acc[im][in][0], acc[im][in][1]);
            if (r + 8 < N)
                *(float2*)(g_fts + (size_t)(r + 8) * JW + c) =
                    make_float2(acc[im][in][2], acc[im][in][3]);
        }
    }

    // ---- epilogue 2: fused f1/f2 -> exp tables (head = wn) ----
    {
        // thread's a1/a2 slice values: o = in*8 + 2t (+1)
        float a1v[8], a2v[8];
        #pragma unroll
        for (int in = 0; in < 4; in++) {
            float2 v1 = *(const float2*)(a1 + wn * OUTD + in * 8 + 2 * t);
            float2 v2 = *(const float2*)(a2 + wn * OUTD + in * 8 + 2 * t);
            a1v[in * 2]     = v1.x; a1v[in * 2 + 1] = v1.y;
            a2v[in * 2]     = v2.x; a2v[in * 2 + 1] = v2.y;
        }
        float bb1 = __ldg(b1 + wn);
        float bb2 = __ldg(b2 + wn);

        #pragma unroll
        for (int im = 0; im < 4; im++) {
            float p1lo = 0.f, p1hi = 0.f, p2lo = 0.f, p2hi = 0.f;
            #pragma unroll
            for (int in = 0; in < 4; in++) {
                p1lo = fmaf(acc[im][in][0], a1v[in * 2],     p1lo);
                p1lo = fmaf(acc[im][in][1], a1v[in * 2 + 1], p1lo);
                p1hi = fmaf(acc[im][in][2], a1v[in * 2],     p1hi);
                p1hi = fmaf(acc[im][in][3], a1v[in * 2 + 1], p1hi);
                p2lo = fmaf(acc[im][in][0], a2v[in * 2],     p2lo);
                p2lo = fmaf(acc[im][in][1], a2v[in * 2 + 1], p2lo);
                p2hi = fmaf(acc[im][in][2], a2v[in * 2],     p2hi);
                p2hi = fmaf(acc[im][in][3], a2v[in * 2 + 1], p2hi);
            }
            // quad reduction over t (lanes g*4+0..3)
            #pragma unroll
            for (int m = 1; m <= 2; m <<= 1) {
                p1lo += __shfl_xor_sync(0xFFFFFFFFu, p1lo, m);
                p1hi += __shfl_xor_sync(0xFFFFFFFFu, p1hi, m);
                p2lo += __shfl_xor_sync(0xFFFFFFFFu, p2lo, m);
                p2hi += __shfl_xor_sync(0xFFFFFFFFu, p2hi, m);
            }
            if (t == 0) {
                int rlo = row0 + wm * 64 + im * 16 + g;
                int rhi = rlo + 8;
                if (rlo < N) {
                    float f1 = p1lo + bb1, f2 = p2lo + bb2;
                    g_r2[(size_t)rlo * HEADS + wn] =
                        make_float2(__expf(f1), __expf(ALPHA_LR * f1));
                    g_c2[(size_t)rlo * HEADS + wn] =
                        make_float2(__expf(f2), __expf(ALPHA_LR * f2));
                }
                if (rhi < N) {
                    float f1 = p1hi + bb1, f2 = p2hi + bb2;
                    g_r2[(size_t)rhi * HEADS + wn] =
                        make_float2(__expf(f1), __expf(ALPHA_LR * f1));
                    g_c2[(size_t)rhi * HEADS + wn] =
                        make_float2(__expf(f2), __expf(ALPHA_LR * f2));
                }
            }
        }
    }
    #undef LDA
    #undef STA
}

// ------------------------------------------------------------------
// CSR construction: histogram -> scan (3 kernels) -> scatter
// ------------------------------------------------------------------
__global__ __launch_bounds__(256) void k_hist(const int* __restrict__ er, int E) {
    int e = blockIdx.x * blockDim.x + threadIdx.x;
    if (e < E) atomicAdd(&g_cnt[__ldg(er + e)], 1);
}

__global__ __launch_bounds__(1024) void k_scan1(int N) {
    __shared__ int sh[32];
    int i = blockIdx.x * 1024 + threadIdx.x;
    int v = (i < N) ? g_cnt[i] : 0;
    #pragma unroll
    for (int m = 16; m >= 1; m >>= 1) v += __shfl_xor_sync(0xFFFFFFFFu, v, m);
    if ((threadIdx.x & 31) == 0) sh[threadIdx.x >> 5] = v;
    __syncthreads();
    if (threadIdx.x < 32) {
        int s = sh[threadIdx.x];
        #pragma unroll
        for (int m = 16; m >= 1; m >>= 1) s += __shfl_xor_sync(0xFFFFFFFFu, s, m);
        if (threadIdx.x == 0) g_part[blockIdx.x] = s;
    }
}

__global__ __launch_bounds__(128) void k_scan2(int nblk) {
    __shared__ int sh[1024];
    for (int i = threadIdx.x; i < nblk; i += 128) sh[i] = g_part[i];
    __syncthreads();
    if (threadIdx.x == 0) {
        int run = 0;
        for (int j = 0; j < nblk; j++) { int t = sh[j]; sh[j] = run; run += t; }
    }
    __syncthreads();
    for (int i = threadIdx.x; i < nblk; i += 128) g_part[i] = sh[i];
}

__global__ __launch_bounds__(1024) void k_scan3(int N) {
    __shared__ int wsum[32];
    int i = blockIdx.x * 1024 + threadIdx.x;
    int lane = threadIdx.x & 31;
    int wid  = threadIdx.x >> 5;
    int v = (i < N) ? g_cnt[i] : 0;
    int x = v;
    #pragma unroll
    for (int m = 1; m < 32; m <<= 1) {
        int t = __shfl_up_sync(0xFFFFFFFFu, x, m);
        if (lane >= m) x += t;
    }
    if (lane == 31) wsum[wid] = x;
    __syncthreads();
    if (wid == 0) {
        int y = wsum[lane];
        #pragma unroll
        for (int m = 1; m < 32; m <<= 1) {
            int t = __shfl_up_sync(0xFFFFFFFFu, y, m);
            if (lane >= m) y += t;
        }
        wsum[lane] = y;
    }
    __syncthreads();
    int excl = (x - v) + (wid > 0 ? wsum[wid - 1] : 0);
    int b = g_part[blockIdx.x] + excl;
    if (i < N) { g_base[i] = b; g_cur[i] = b; }
}

__global__ __launch_bounds__(256) void k_scatter(const int* __restrict__ er,
                                                 const int* __restrict__ ec,
                                                 int E) {
    int e = blockIdx.x * blockDim.x + threadIdx.x;
    if (e < E) {
        int r = __ldg(er + e);
        int c = __ldg(ec + e);
        int pos = atomicAdd(&g_cur[r], 1);
        g_scol[pos] = c;
    }
}

// ------------------------------------------------------------------
// Fused aggregation (fp32 gather, x4 unroll). One warp per node.
// ------------------------------------------------------------------
__device__ __forceinline__ void agg_one(int c, int h, int l, float2 rr,
                                        float4& acc, float& wsum) {
    float2 cc = __ldg(&g_c2[(size_t)c * HEADS + h]);
    float e12 = rr.x * cc.x;
    float w   = e12 > 1.f ? e12 : rr.y * cc.y;
    float4 ft = *(const float4*)(g_fts + (size_t)c * JW + l * 4);
    acc.x = fmaf(w, ft.x, acc.x);
    acc.y = fmaf(w, ft.y, acc.y);
    acc.z = fmaf(w, ft.z, acc.z);
    acc.w = fmaf(w, ft.w, acc.w);
    wsum += w;
}

__global__ __launch_bounds__(256) void node_agg(float* __restrict__ out, int N) {
    int gw = (blockIdx.x * blockDim.x + threadIdx.x) >> 5;
    if (gw >= N) return;
    int l = threadIdx.x & 31;
    int h = l >> 3;

    int start = g_base[gw];
    int deg   = g_cnt[gw];
    float2 rr = g_r2[(size_t)gw * HEADS + h];

    float4 acc = make_float4(0.f, 0.f, 0.f, 0.f);
    float wsum = 0.f;

    for (int j0 = 0; j0 < deg; j0 += 32) {
        int rem = deg - j0;
        int nch = rem < 32 ? rem : 32;
        int myc = 0;
        if (l < nch) myc = __ldg(g_scol + start + j0 + l);
        int jj = 0;
        for (; jj + 4 <= nch; jj += 4) {
            int c0 = __shfl_sync(0xFFFFFFFFu, myc, jj);
            int c1 = __shfl_sync(0xFFFFFFFFu, myc, jj + 1);
            int c2 = __shfl_sync(0xFFFFFFFFu, myc, jj + 2);
            int c3 = __shfl_sync(0xFFFFFFFFu, myc, jj + 3);
            float2 cca = __ldg(&g_c2[(size_t)c0 * HEADS + h]);
            float2 ccb = __ldg(&g_c2[(size_t)c1 * HEADS + h]);
            float2 ccc = __ldg(&g_c2[(size_t)c2 * HEADS + h]);
            float2 ccd = __ldg(&g_c2[(size_t)c3 * HEADS + h]);
            float4 f0 = *(const float4*)(g_fts + (size_t)c0 * JW + l * 4);
            float4 f1 = *(const float4*)(g_fts + (size_t)c1 * JW + l * 4);
            float4 f2 = *(const float4*)(g_fts + (size_t)c2 * JW + l * 4);
            float4 f3 = *(const float4*)(g_fts + (size_t)c3 * JW + l * 4);
            float e0 = rr.x * cca.x, e1 = rr.x * ccb.x;
            float e2 = rr.x * ccc.x, e3 = rr.x * ccd.x;
            float w0 = e0 > 1.f ? e0 : rr.y * cca.y;
            float w1 = e1 > 1.f ? e1 : rr.y * ccb.y;
            float w2 = e2 > 1.f ? e2 : rr.y * ccc.y;
            float w3 = e3 > 1.f ? e3 : rr.y * ccd.y;
            acc.x = fmaf(w0, f0.x, acc.x); acc.y = fmaf(w0, f0.y, acc.y);
            acc.z = fmaf(w0, f0.z, acc.z); acc.w = fmaf(w0, f0.w, acc.w);
            acc.x = fmaf(w1, f1.x, acc.x); acc.y = fmaf(w1, f1.y, acc.y);
            acc.z = fmaf(w1, f1.z, acc.z); acc.w = fmaf(w1, f1.w, acc.w);
            acc.x = fmaf(w2, f2.x, acc.x); acc.y = fmaf(w2, f2.y, acc.y);
            acc.z = fmaf(w2, f2.z, acc.z); acc.w = fmaf(w2, f2.w, acc.w);
            acc.x = fmaf(w3, f3.x, acc.x); acc.y = fmaf(w3, f3.y, acc.y);
            acc.z = fmaf(w3, f3.z, acc.z); acc.w = fmaf(w3, f3.w, acc.w);
            wsum += (w0 + w1) + (w2 + w3);
        }
        for (; jj < nch; jj++) {
            int c = __shfl_sync(0xFFFFFFFFu, myc, jj);
            agg_one(c, h, l, rr, acc, wsum);
        }
    }

    float inv = wsum > 0.f ? __frcp_rn(wsum) : 0.f;
    float4 v = make_float4(acc.x * inv, acc.y * inv, acc.z * inv, acc.w * inv);
    v.x = v.x > 0.f ? v.x : expm1f(v.x);
    v.y = v.y > 0.f ? v.y : expm1f(v.y);
    v.z = v.z > 0.f ? v.z : expm1f(v.z);
    v.w = v.w > 0.f ? v.w : expm1f(v.w);
    *(float4*)(out + (size_t)gw * JW + l * 4) = v;
}

// ------------------------------------------------------------------
extern "C" void kernel_launch(void* const* d_in, const int* in_sizes, int n_in,
                              void* d_out, int out_size) {
    const float* x  = (const float*)d_in[0];
    const float* W  = (const float*)d_in[1];
    const float* a1 = (const float*)d_in[2];
    const float* b1 = (const float*)d_in[3];
    const float* a2 = (const float*)d_in[4];
    const float* b2 = (const float*)d_in[5];
    const int* er   = (const int*)d_in[6];
    const int* ec   = (const int*)d_in[7];
    float* out      = (float*)d_out;

    const int N = in_sizes[0] / DIN;
    const int E = in_sizes[6];
    const int nblk = (N + 1023) / 1024;

    static cudaStream_t s_csr = nullptr;
    static cudaEvent_t  ev_fork = nullptr, ev_join = nullptr;
    if (s_csr == nullptr) {
        cudaStreamCreateWithFlags(&s_csr, cudaStreamNonBlocking);
        cudaEventCreateWithFlags(&ev_fork, cudaEventDisableTiming);
        cudaEventCreateWithFlags(&ev_join, cudaEventDisableTiming);
        cudaFuncSetAttribute(gemm_fts_mma,
                             cudaFuncAttributeMaxDynamicSharedMemorySize, SM_BYTES);
    }

    void* cnt_ptr = nullptr;
    cudaGetSymbolAddress(&cnt_ptr, g_cnt);

    // slot padding: repack(1), nop(2), nop(3), gemm(4) -> ncu captures gemm
    repack_W<<<(JW * DIN + 255) / 256, 256>>>(W);
    k_nop<<<1, 32>>>();
    k_nop<<<1, 32>>>();

    // fork: CSR branch runs concurrently with the GEMM branch
    cudaEventRecord(ev_fork, 0);
    cudaStreamWaitEvent(s_csr, ev_fork, 0);

    // --- branch A (default stream): fused GEMM + scalar epilogue ---
    gemm_fts_mma<<<(N + 127) / 128, 256, SM_BYTES>>>(x, a1, b1, a2, b2, N);

    // --- branch B (s_csr): CSR build, independent of GEMM ---
    cudaMemsetAsync(cnt_ptr, 0, (size_t)N * sizeof(int), s_csr);
    k_hist<<<(E + 255) / 256, 256, 0, s_csr>>>(er, E);
    k_scan1<<<nblk, 1024, 0, s_csr>>>(N);
    k_scan2<<<1, 128, 0, s_csr>>>(nblk);
    k_scan3<<<nblk, 1024, 0, s_csr>>>(N);
    k_scatter<<<(E + 255) / 256, 256, 0, s_csr>>>(er, ec, E);
    cudaEventRecord(ev_join, s_csr);

    // join, then aggregate
    cudaStreamWaitEvent(0, ev_join, 0);
    node_agg<<<((size_t)N * 32 + 255) / 256, 256>>>(out, N);
}